// round 1
// baseline (speedup 1.0000x reference)
#include <cuda_runtime.h>
#include <math.h>

#define NPB 65536
#define NT  131072

// ---------------- scratch (device globals; no allocation allowed) ----------
__device__ float g_X [NT*64];     // activation NHWC
__device__ float g_Mk[NT*64];     // mask NHWC
__device__ float g_Q [NT*64];
__device__ float g_K [NT*64];
__device__ float g_V [NT*64];
__device__ float g_T1[NT*64];
__device__ float g_T2[NT*64];
__device__ float g_H1[NT*256];
__device__ float g_H2[NT*256];
__device__ float g_GP[2*128*1152]; // gram partials: 1024 S + 64 |q|^2 + 64 |k|^2
__device__ float g_MC[2*64*64];    // per-batch combined attn^T @ Wp

__device__ __forceinline__ float gelu_f(float u){
    return 0.5f*u*(1.f+erff(u*0.70710678118654752f));
}

// ---------------- transposes ----------------
__global__ __launch_bounds__(256) void k_nchw2nhwc(const float* __restrict__ in, float* __restrict__ out){
    __shared__ float t[32][33];
    int tx = threadIdx.x & 31, ty = threadIdx.x >> 5;
    int pt = blockIdx.x, ct = blockIdx.y, b = blockIdx.z;
    const float* ip = in  + (size_t)b*64*NPB;
    float*       op = out + (size_t)b*NPB*64;
    #pragma unroll
    for(int r=0;r<4;r++){
        int c = ct*32 + ty + r*8;
        t[ty+r*8][tx] = ip[(size_t)c*NPB + (size_t)pt*32 + tx];
    }
    __syncthreads();
    #pragma unroll
    for(int r=0;r<4;r++){
        int p = pt*32 + ty + r*8;
        op[(size_t)p*64 + ct*32 + tx] = t[tx][ty+r*8];
    }
}

__global__ __launch_bounds__(256) void k_nhwc2nchw(const float* __restrict__ in, float* __restrict__ out){
    __shared__ float t[32][33];
    int tx = threadIdx.x & 31, ty = threadIdx.x >> 5;
    int pt = blockIdx.x, ct = blockIdx.y, b = blockIdx.z;
    const float* ip = in  + (size_t)b*NPB*64;
    float*       op = out + (size_t)b*64*NPB;
    #pragma unroll
    for(int r=0;r<4;r++){
        int p = pt*32 + ty + r*8;
        t[ty+r*8][tx] = ip[(size_t)p*64 + ct*32 + tx];
    }
    __syncthreads();
    #pragma unroll
    for(int r=0;r<4;r++){
        int c = ct*32 + ty + r*8;
        op[(size_t)c*NPB + (size_t)pt*32 + tx] = t[tx][ty+r*8];
    }
}

// ---------------- generic 64x64 matmul: out[n,:] = X[n,:] @ W (+bias) ------
__global__ __launch_bounds__(256) void k_mat64(const float* __restrict__ X,
        const float* __restrict__ W, const float* __restrict__ bias,
        float* __restrict__ out, int perBatchW){
    __shared__ float sW[4096];
    int tid = threadIdx.x;
    const float* Wp = W + ((perBatchW && blockIdx.x >= 256) ? 4096 : 0);
    #pragma unroll
    for(int i=0;i<16;i++) sW[tid + i*256] = Wp[tid + i*256];
    __syncthreads();
    size_t n = (size_t)blockIdx.x*256 + tid;
    const float4* xp = (const float4*)(X + n*64);
    float4* o4 = (float4*)(out + n*64);
    for(int cb=0;cb<4;cb++){
        float acc[16];
        #pragma unroll
        for(int k=0;k<16;k++) acc[k] = bias ? bias[cb*16+k] : 0.f;
        #pragma unroll 4
        for(int j4=0;j4<16;j4++){
            float4 xv = xp[j4];
            const float* w0 = &sW[(j4*4)*64 + cb*16];
            #pragma unroll
            for(int k=0;k<16;k++){
                acc[k] += xv.x * w0[k];
                acc[k] += xv.y * w0[64+k];
                acc[k] += xv.z * w0[128+k];
                acc[k] += xv.w * w0[192+k];
            }
        }
        #pragma unroll
        for(int q=0;q<4;q++)
            o4[cb*4+q] = make_float4(acc[4*q],acc[4*q+1],acc[4*q+2],acc[4*q+3]);
    }
}

// ---------------- gram partials: per (b,head) 16x16 K.Q^T + channel norms --
__global__ __launch_bounds__(256) void k_gram(const float* __restrict__ Q,
        const float* __restrict__ K, float* __restrict__ gpart){
    __shared__ float sq[4096], sk[4096];
    __shared__ float pS[1024];
    __shared__ float pn[128];
    int tid = threadIdx.x;
    int b = blockIdx.y;
    for(int i=tid;i<1024;i+=256) pS[i]=0.f;
    if(tid<128) pn[tid]=0.f;
    for(int t=0;t<8;t++){
        size_t base = ((size_t)b*NPB + (size_t)blockIdx.x*512 + t*64)*64;
        __syncthreads();
        for(int i=tid;i<4096;i+=256){ sq[i]=Q[base+i]; sk[i]=K[base+i]; }
        __syncthreads();
        #pragma unroll
        for(int jj=0;jj<4;jj++){
            int job = tid + jj*256;
            int h=job>>8, d=(job>>4)&15, e=job&15;
            int ck=h*16+d, cq=h*16+e;
            float acc=0.f;
            #pragma unroll 8
            for(int p=0;p<64;p++) acc += sk[p*64+ck]*sq[p*64+cq];
            pS[job]+=acc;
        }
        if(tid<128){
            int c=tid&63;
            const float* s = (tid<64)? sq : sk;
            float acc=0.f;
            #pragma unroll 8
            for(int p=0;p<64;p++){ float v=s[p*64+c]; acc+=v*v; }
            pn[tid]+=acc;
        }
    }
    __syncthreads();
    float* gp = gpart + ((size_t)b*128 + blockIdx.x)*1152;
    for(int i=tid;i<1024;i+=256) gp[i]=pS[i];
    if(tid<128) gp[1024+tid]=pn[tid];
}

// ---------------- attn softmax + fold into Mcomb = B @ Wp ------------------
__global__ __launch_bounds__(256) void k_attn(const float* __restrict__ gpart,
        const float* __restrict__ Wp, const float* __restrict__ resc,
        float* __restrict__ Mcomb){
    __shared__ float sred[2304];
    __shared__ float sa[2048];
    int tid = threadIdx.x;
    for(int jj=tid;jj<2304;jj+=256){
        int b=jj/1152, j=jj-b*1152;
        float acc=0.f;
        for(int blk=0;blk<128;blk++) acc += gpart[((size_t)b*128+blk)*1152 + j];
        sred[jj]=acc;
    }
    __syncthreads();
    if(tid<128){
        int b=tid>>6, hd=tid&63, h=hd>>4, d=hd&15;
        float nk = fmaxf(sqrtf(sred[b*1152+1088+hd]),1e-6f);
        float r = resc[h];
        float row[16]; float mx=-1e30f;
        #pragma unroll
        for(int e=0;e<16;e++){
            float nq = fmaxf(sqrtf(sred[b*1152+1024+h*16+e]),1e-6f);
            float v = sred[b*1152 + h*256 + d*16 + e] / (nk*nq) * r;
            row[e]=v; mx=fmaxf(mx,v);
        }
        float s=0.f;
        #pragma unroll
        for(int e=0;e<16;e++){ row[e]=expf(row[e]-mx); s+=row[e]; }
        float inv=1.f/s;
        #pragma unroll
        for(int e=0;e<16;e++) sa[((b*4+h)*16+d)*16+e] = row[e]*inv;
    }
    __syncthreads();
    // Mcomb[b][h*16+e][co] = sum_d attn[b,h,d,e] * Wp[(h*16+d)*64+co]
    for(int job=tid;job<8192;job+=256){
        int b=job>>12, rem=job&4095, ci=rem>>6, co=rem&63;
        int h=ci>>4, e=ci&15;
        float acc=0.f;
        #pragma unroll
        for(int d=0;d<16;d++) acc += sa[((b*4+h)*16+d)*16+e] * Wp[(h*16+d)*64+co];
        Mcomb[job]=acc;
    }
}

// ---------------- mask gate: VG = V * m1 * (1 + sigmoid(dw5(T)+db)) --------
__global__ __launch_bounds__(256) void k_maskgate(const float* __restrict__ T,
        const float* __restrict__ M1, const float* __restrict__ V,
        const float* __restrict__ dw, const float* __restrict__ db,
        float* __restrict__ VG){
    __shared__ float sdw[1600];
    __shared__ float sdb[64];
    int tid=threadIdx.x;
    for(int i=tid;i<1600;i+=256) sdw[i]=dw[i];
    if(tid<64) sdb[tid]=db[tid];
    __syncthreads();
    size_t idx=(size_t)blockIdx.x*256+tid;
    int c=(int)(idx&63);
    size_t p=idx>>6;
    int b=(int)(p>>16);
    int pp=(int)(p&65535);
    int y=pp>>8, x=pp&255;
    float conv=0.f;
    #pragma unroll
    for(int dy=0;dy<5;dy++){
        int yy=y+dy-2; if(yy<0||yy>255) continue;
        #pragma unroll
        for(int dx=0;dx<5;dx++){
            int xx=x+dx-2; if(xx<0||xx>255) continue;
            conv += T[((((size_t)b<<16)+(yy<<8)+xx)<<6)+c]*sdw[(dy*5+dx)*64+c];
        }
    }
    float am = 1.f/(1.f+expf(-(conv+sdb[c])));
    VG[idx] = V[idx]*M1[idx]*(1.f+am);
}

// ---------------- depthwise 3x3 + GELU (C = 1<<cbits) ----------------------
__global__ __launch_bounds__(256) void k_dw3_gelu(const float* __restrict__ in,
        const float* __restrict__ dw, float* __restrict__ out, int cbits){
    __shared__ float sdw[2304];
    int tid=threadIdx.x;
    int Cc=1<<cbits;
    for(int i=tid;i<9*Cc;i+=256) sdw[i]=dw[i];
    __syncthreads();
    size_t idx=(size_t)blockIdx.x*256+tid;
    int c=(int)(idx&(Cc-1));
    size_t p=idx>>cbits;
    int b=(int)(p>>16), pp=(int)(p&65535), y=pp>>8, x=pp&255;
    float conv=0.f;
    #pragma unroll
    for(int dy=0;dy<3;dy++){
        int yy=y+dy-1; if(yy<0||yy>255) continue;
        #pragma unroll
        for(int dx=0;dx<3;dx++){
            int xx=x+dx-1; if(xx<0||xx>255) continue;
            conv += in[((((size_t)b<<16)+(yy<<8)+xx)<<cbits)+c]*sdw[(dy*3+dx)*Cc+c];
        }
    }
    out[idx]=gelu_f(conv);
}

// ---------------- msa epilogue: X += OC + dw3(P, pe2) ----------------------
__global__ __launch_bounds__(256) void k_msa_out(const float* __restrict__ OC,
        const float* __restrict__ P, const float* __restrict__ pe2,
        float* __restrict__ X){
    __shared__ float sdw[576];
    int tid=threadIdx.x;
    for(int i=tid;i<576;i+=256) sdw[i]=pe2[i];
    __syncthreads();
    size_t idx=(size_t)blockIdx.x*256+tid;
    int c=(int)(idx&63);
    size_t p=idx>>6;
    int b=(int)(p>>16), pp=(int)(p&65535), y=pp>>8, x=pp&255;
    float conv=0.f;
    #pragma unroll
    for(int dy=0;dy<3;dy++){
        int yy=y+dy-1; if(yy<0||yy>255) continue;
        #pragma unroll
        for(int dx=0;dx<3;dx++){
            int xx=x+dx-1; if(xx<0||xx>255) continue;
            conv += P[((((size_t)b<<16)+(yy<<8)+xx)<<6)+c]*sdw[(dy*3+dx)*64+c];
        }
    }
    X[idx] += OC[idx] + conv;
}

// ---------------- LN + 64->256 expand chunk + GELU -------------------------
__global__ __launch_bounds__(256) void k_ff1(const float* __restrict__ X,
        const float* __restrict__ W, const float* __restrict__ g,
        const float* __restrict__ bb, float* __restrict__ H1){
    __shared__ float sW[4096];
    __shared__ float sg[64], sb[64];
    int tid=threadIdx.x;
    int ch=blockIdx.y;
    for(int i=tid;i<4096;i+=256) sW[i]=W[(i>>6)*256 + ch*64 + (i&63)];
    if(tid<64){ sg[tid]=g[tid]; sb[tid]=bb[tid]; }
    __syncthreads();
    size_t n=(size_t)blockIdx.x*256+tid;
    const float4* xp=(const float4*)(X+n*64);
    float mu=0.f, m2=0.f;
    #pragma unroll 4
    for(int j4=0;j4<16;j4++){
        float4 v=xp[j4];
        mu += v.x+v.y+v.z+v.w;
        m2 += v.x*v.x+v.y*v.y+v.z*v.z+v.w*v.w;
    }
    mu *= (1.f/64.f);
    float var = fmaxf(m2*(1.f/64.f) - mu*mu, 0.f);
    float rs = rsqrtf(var + 1e-5f);
    float* op = H1 + n*256 + ch*64;
    for(int cb=0;cb<4;cb++){
        float acc[16];
        #pragma unroll
        for(int k=0;k<16;k++) acc[k]=0.f;
        #pragma unroll 4
        for(int j4=0;j4<16;j4++){
            float4 xv=xp[j4];
            int j=j4*4;
            float x0=(xv.x-mu)*rs*sg[j]  +sb[j];
            float x1=(xv.y-mu)*rs*sg[j+1]+sb[j+1];
            float x2=(xv.z-mu)*rs*sg[j+2]+sb[j+2];
            float x3=(xv.w-mu)*rs*sg[j+3]+sb[j+3];
            const float* w0=&sW[j*64+cb*16];
            #pragma unroll
            for(int k=0;k<16;k++){
                acc[k]+=x0*w0[k];
                acc[k]+=x1*w0[64+k];
                acc[k]+=x2*w0[128+k];
                acc[k]+=x3*w0[192+k];
            }
        }
        #pragma unroll
        for(int k=0;k<16;k++) op[cb*16+k]=gelu_f(acc[k]);
    }
}

// ---------------- 256->64 project + residual -------------------------------
__global__ __launch_bounds__(256) void k_ff2(const float* __restrict__ H2,
        const float* __restrict__ W, float* __restrict__ X){
    __shared__ float sW[4096];
    int tid=threadIdx.x;
    size_t n=(size_t)blockIdx.x*256+tid;
    float acc[64];
    #pragma unroll
    for(int k=0;k<64;k++) acc[k]=0.f;
    for(int jc=0;jc<4;jc++){
        __syncthreads();
        #pragma unroll
        for(int i=0;i<16;i++) sW[tid+i*256]=W[jc*4096 + tid+i*256];
        __syncthreads();
        const float4* h4=(const float4*)(H2 + n*256 + jc*64);
        #pragma unroll 2
        for(int j4=0;j4<16;j4++){
            float4 hv=h4[j4];
            const float* w0=&sW[(j4*4)*64];
            #pragma unroll
            for(int k=0;k<64;k++){
                acc[k]+=hv.x*w0[k];
                acc[k]+=hv.y*w0[64+k];
                acc[k]+=hv.z*w0[128+k];
                acc[k]+=hv.w*w0[192+k];
            }
        }
    }
    float4* o4=(float4*)(X+n*64);
    #pragma unroll
    for(int q=0;q<16;q++){
        float4 v=o4[q];
        v.x+=acc[4*q]; v.y+=acc[4*q+1]; v.z+=acc[4*q+2]; v.w+=acc[4*q+3];
        o4[q]=v;
    }
}

// ---------------- host -----------------------------------------------------
extern "C" void kernel_launch(void* const* d_in, const int* in_sizes, int n_in,
                              void* d_out, int out_size){
    const float* x    = (const float*)d_in[0];
    const float* mask = (const float*)d_in[1];
    const float* Wq   = (const float*)d_in[2];
    const float* Wk   = (const float*)d_in[3];
    const float* Wv   = (const float*)d_in[4];
    const float* resc = (const float*)d_in[5];
    const float* Wp   = (const float*)d_in[6];
    const float* bp   = (const float*)d_in[7];
    const float* pe1  = (const float*)d_in[8];
    const float* pe2  = (const float*)d_in[9];
    const float* mw1  = (const float*)d_in[10];
    const float* mb1  = (const float*)d_in[11];
    const float* mw2  = (const float*)d_in[12];
    const float* mb2  = (const float*)d_in[13];
    const float* mdw  = (const float*)d_in[14];
    const float* mdb  = (const float*)d_in[15];
    const float* lng  = (const float*)d_in[16];
    const float* lnb  = (const float*)d_in[17];
    const float* fw1  = (const float*)d_in[18];
    const float* fdw  = (const float*)d_in[19];
    const float* fw2  = (const float*)d_in[20];
    float* out = (float*)d_out;

    float *pX,*pM,*pQ,*pK,*pV,*pT1,*pT2,*pH1,*pH2,*pGP,*pMC;
    cudaGetSymbolAddress((void**)&pX,  g_X);
    cudaGetSymbolAddress((void**)&pM,  g_Mk);
    cudaGetSymbolAddress((void**)&pQ,  g_Q);
    cudaGetSymbolAddress((void**)&pK,  g_K);
    cudaGetSymbolAddress((void**)&pV,  g_V);
    cudaGetSymbolAddress((void**)&pT1, g_T1);
    cudaGetSymbolAddress((void**)&pT2, g_T2);
    cudaGetSymbolAddress((void**)&pH1, g_H1);
    cudaGetSymbolAddress((void**)&pH2, g_H2);
    cudaGetSymbolAddress((void**)&pGP, g_GP);
    cudaGetSymbolAddress((void**)&pMC, g_MC);

    dim3 tg(2048,2,2);
    k_nchw2nhwc<<<tg,256>>>(x,    pX);
    k_nchw2nhwc<<<tg,256>>>(mask, pM);

    for(int i=0;i<3;i++){
        const float* Wq_i  = Wq  + i*4096;
        const float* Wk_i  = Wk  + i*4096;
        const float* Wv_i  = Wv  + i*4096;
        const float* Wp_i  = Wp  + i*4096;
        const float* mw1_i = mw1 + i*4096;
        const float* mw2_i = mw2 + i*4096;
        const float* bp_i  = bp  + i*64;
        const float* mb1_i = mb1 + i*64;
        const float* mb2_i = mb2 + i*64;
        const float* mdb_i = mdb + i*64;
        const float* lng_i = lng + i*64;
        const float* lnb_i = lnb + i*64;
        const float* pe1_i = pe1 + i*576;
        const float* pe2_i = pe2 + i*576;
        const float* mdw_i = mdw + i*1600;
        const float* rs_i  = resc+ i*4;
        const float* fw1_i = fw1 + i*64*256;
        const float* fdw_i = fdw + i*9*256;
        const float* fw2_i = fw2 + i*256*64;

        // attention stats path
        k_mat64<<<512,256>>>(pX, Wq_i, nullptr, pQ, 0);
        k_mat64<<<512,256>>>(pX, Wk_i, nullptr, pK, 0);
        k_gram<<<dim3(128,2),256>>>(pQ, pK, pGP);
        k_attn<<<1,256>>>(pGP, Wp_i, rs_i, pMC);
        // v + mask gate
        k_mat64<<<512,256>>>(pX, Wv_i, nullptr, pV, 0);
        k_mat64<<<512,256>>>(pM, mw1_i, mb1_i, pT1, 0);
        k_mat64<<<512,256>>>(pT1, mw2_i, mb2_i, pT2, 0);
        k_maskgate<<<32768,256>>>(pT2, pT1, pV, mdw_i, mdb_i, pQ);   // VG -> g_Q
        // positional path
        k_dw3_gelu<<<32768,256>>>(pV, pe1_i, pK, 6);                 // P -> g_K
        // attention apply + proj (folded), then epilogue
        k_mat64<<<512,256>>>(pQ, pMC, bp_i, pT1, 1);                 // OC -> g_T1
        k_msa_out<<<32768,256>>>(pT1, pK, pe2_i, pX);                // X += OC + dw3(P)
        // feed-forward
        k_ff1<<<dim3(512,4),256>>>(pX, fw1_i, lng_i, lnb_i, pH1);
        k_dw3_gelu<<<131072,256>>>(pH1, fdw_i, pH2, 8);
        k_ff2<<<512,256>>>(pH2, fw2_i, pX);
    }

    k_nhwc2nchw<<<tg,256>>>(pX, out);
}

// round 2
// speedup vs baseline: 1.3147x; 1.3147x over previous
#include <cuda_runtime.h>
#include <math.h>

#define NPB 65536
#define NT  131072
typedef unsigned long long ull;

// ---------------- scratch (device globals; no allocation allowed) ----------
__device__ float g_X [NT*64];
__device__ float g_Mk[NT*64];
__device__ float g_Q [NT*64];
__device__ float g_K [NT*64];
__device__ float g_V [NT*64];
__device__ float g_T1[NT*64];
__device__ float g_T2[NT*64];
__device__ float g_H1[NT*256];
__device__ float g_H2[NT*256];
__device__ float g_GP[2*128*1152];
__device__ float g_MC[2*64*64];

__device__ __forceinline__ float gelu_f(float u){
    return 0.5f*u*(1.f+erff(u*0.70710678118654752f));
}
__device__ __forceinline__ ull pk2(float lo, float hi){
    ull r; asm("mov.b64 %0, {%1,%2};" : "=l"(r) : "f"(lo), "f"(hi)); return r;
}
__device__ __forceinline__ void upk2(ull v, float&lo, float&hi){
    asm("mov.b64 {%0,%1}, %2;" : "=f"(lo), "=f"(hi) : "l"(v));
}
#define FMA2(acc, a, b) asm("fma.rn.f32x2 %0, %1, %2, %0;" : "+l"(acc) : "l"(a), "l"(b))

// ---------------- transposes ----------------
__global__ __launch_bounds__(256) void k_nchw2nhwc(const float* __restrict__ in, float* __restrict__ out){
    __shared__ float t[32][33];
    int tx = threadIdx.x & 31, ty = threadIdx.x >> 5;
    int pt = blockIdx.x, ct = blockIdx.y, b = blockIdx.z;
    const float* ip = in  + (size_t)b*64*NPB;
    float*       op = out + (size_t)b*NPB*64;
    #pragma unroll
    for(int r=0;r<4;r++){
        int c = ct*32 + ty + r*8;
        t[ty+r*8][tx] = ip[(size_t)c*NPB + (size_t)pt*32 + tx];
    }
    __syncthreads();
    #pragma unroll
    for(int r=0;r<4;r++){
        int p = pt*32 + ty + r*8;
        op[(size_t)p*64 + ct*32 + tx] = t[tx][ty+r*8];
    }
}
__global__ __launch_bounds__(256) void k_nhwc2nchw(const float* __restrict__ in, float* __restrict__ out){
    __shared__ float t[32][33];
    int tx = threadIdx.x & 31, ty = threadIdx.x >> 5;
    int pt = blockIdx.x, ct = blockIdx.y, b = blockIdx.z;
    const float* ip = in  + (size_t)b*NPB*64;
    float*       op = out + (size_t)b*64*NPB;
    #pragma unroll
    for(int r=0;r<4;r++){
        int p = pt*32 + ty + r*8;
        t[ty+r*8][tx] = ip[(size_t)p*64 + ct*32 + tx];
    }
    __syncthreads();
    #pragma unroll
    for(int r=0;r<4;r++){
        int c = ct*32 + ty + r*8;
        op[(size_t)c*NPB + (size_t)pt*32 + tx] = t[tx][ty+r*8];
    }
}

// ---------------- tiled FFMA2 GEMM ----------------------------------------
// Tile: 256 pixels x 64 outputs per block, 128 threads.
// Thread (og = t>>4, pg = t&15): outputs [og*8, og*8+8), pixel pairs pg+16*i.
// MODE: 0 = store, 1 = gelu+store, 2 = add to OUT (residual).
// IN_CHUNKS: input channels = 64*IN_CHUNKS (K-chunked, acc in regs).
// Output-column chunk via blockIdx.y (offset blockIdx.y*64 into W cols & OUT cols).
#define GSM_X   (64*258)            // floats, stride 258 (ull stride 129)
#define GSM_BYTES (GSM_X*4 + 64*64*8)

template<int IN_CHUNKS, int MODE>
__global__ __launch_bounds__(128, 2) void k_gemm(
        const float* __restrict__ X, int xStride,
        const float* __restrict__ W, int wStride, int wBatchStride,
        const float* __restrict__ bias,
        float* __restrict__ OUT, int oStride){
    extern __shared__ char smraw[];
    float* xs = (float*)smraw;
    ull*   wd = (ull*)(smraw + GSM_X*4);
    const int t = threadIdx.x;
    const int og = t >> 4, pg = t & 15;
    const size_t tileBase = (size_t)blockIdx.x * 256;
    const int coOff = blockIdx.y * 64;
    const float* Wp = W + coOff + (wBatchStride ? (int)(tileBase >> 16) * (size_t)wBatchStride : 0);

    ull acc[64];
    if(bias){
        #pragma unroll
        for(int k=0;k<8;k++){
            float bv = bias[og*8+k];
            ull b2 = pk2(bv,bv);
            #pragma unroll
            for(int i=0;i<8;i++) acc[i*8+k] = b2;
        }
    } else {
        #pragma unroll
        for(int q=0;q<64;q++) acc[q] = 0ull;
    }

    for(int jc=0;jc<IN_CHUNKS;jc++){
        if(jc) __syncthreads();
        // stage weights duplicated: wd[j*64 + k] = (w,w)
        for(int s=t;s<4096;s+=128){
            int j = s >> 6, k = s & 63;
            float w = Wp[(size_t)(jc*64 + j)*wStride + k];
            wd[s] = pk2(w,w);
        }
        // stage X tile transposed: xs[j*258 + p]
        for(int s=t;s<8192;s+=128){
            int p = s >> 5, j2 = s & 31;
            float2 v = *(const float2*)(X + (tileBase+p)*xStride + jc*64 + j2*2);
            xs[(j2*2  )*258 + p] = v.x;
            xs[(j2*2+1)*258 + p] = v.y;
        }
        __syncthreads();
        const ull* xs64 = (const ull*)xs;
        for(int j=0;j<64;j++){
            ull xv[8], wv[8];
            const ull* xr = xs64 + j*129 + pg;
            #pragma unroll
            for(int i=0;i<8;i++) xv[i] = xr[16*i];
            const ull* wr = wd + j*64 + og*8;
            #pragma unroll
            for(int k=0;k<8;k++) wv[k] = wr[k];
            #pragma unroll
            for(int i=0;i<8;i++)
                #pragma unroll
                for(int k=0;k<8;k++)
                    FMA2(acc[i*8+k], xv[i], wv[k]);
        }
    }
    // epilogue
    #pragma unroll
    for(int i=0;i<8;i++){
        size_t p0 = tileBase + 2*(pg + 16*i);
        float lo[8], hi[8];
        #pragma unroll
        for(int k=0;k<8;k++) upk2(acc[i*8+k], lo[k], hi[k]);
        if(MODE==1){
            #pragma unroll
            for(int k=0;k<8;k++){ lo[k]=gelu_f(lo[k]); hi[k]=gelu_f(hi[k]); }
        }
        float* o0 = OUT + p0*oStride + coOff + og*8;
        float* o1 = o0 + oStride;
        if(MODE==2){
            #pragma unroll
            for(int k=0;k<8;k++){ lo[k]+=o0[k]; hi[k]+=o1[k]; }
        }
        *(float4*)(o0)   = make_float4(lo[0],lo[1],lo[2],lo[3]);
        *(float4*)(o0+4) = make_float4(lo[4],lo[5],lo[6],lo[7]);
        *(float4*)(o1)   = make_float4(hi[0],hi[1],hi[2],hi[3]);
        *(float4*)(o1+4) = make_float4(hi[4],hi[5],hi[6],hi[7]);
    }
}

// ---------------- coalesced LayerNorm --------------------------------------
__global__ __launch_bounds__(256) void k_ln(const float* __restrict__ X,
        const float* __restrict__ g, const float* __restrict__ b,
        float* __restrict__ O){
    __shared__ float sx[128*66];
    __shared__ float smu[128], srs[128];
    int t = threadIdx.x;
    size_t base = (size_t)blockIdx.x * 128;
    for(int s=t;s<4096;s+=256){
        int p = s >> 5, j2 = s & 31;
        float2 v = *(const float2*)(X + (base+p)*64 + j2*2);
        sx[p*66 + j2*2]   = v.x;
        sx[p*66 + j2*2+1] = v.y;
    }
    __syncthreads();
    if(t<128){
        float mu=0.f, m2=0.f;
        const float* r = sx + t*66;
        #pragma unroll 8
        for(int j=0;j<64;j++){ float v=r[j]; mu+=v; m2+=v*v; }
        mu *= (1.f/64.f);
        float var = fmaxf(m2*(1.f/64.f) - mu*mu, 0.f);
        smu[t]=mu; srs[t]=rsqrtf(var+1e-5f);
    }
    __syncthreads();
    for(int s=t;s<4096;s+=256){
        int p = s >> 5, j2 = s & 31;
        float mu=smu[p], rs=srs[p];
        int j = j2*2;
        float2 v;
        v.x = (sx[p*66+j]  -mu)*rs*g[j]  +b[j];
        v.y = (sx[p*66+j+1]-mu)*rs*g[j+1]+b[j+1];
        *(float2*)(O + (base+p)*64 + j) = v;
    }
}

// ---------------- gram partials --------------------------------------------
__global__ __launch_bounds__(256) void k_gram(const float* __restrict__ Q,
        const float* __restrict__ K, float* __restrict__ gpart){
    __shared__ float sq[4096], sk[4096];
    __shared__ float pS[1024];
    __shared__ float pn[128];
    int tid = threadIdx.x;
    int b = blockIdx.y;
    for(int i=tid;i<1024;i+=256) pS[i]=0.f;
    if(tid<128) pn[tid]=0.f;
    for(int t=0;t<8;t++){
        size_t base = ((size_t)b*NPB + (size_t)blockIdx.x*512 + t*64)*64;
        __syncthreads();
        for(int i=tid;i<4096;i+=256){ sq[i]=Q[base+i]; sk[i]=K[base+i]; }
        __syncthreads();
        #pragma unroll
        for(int jj=0;jj<4;jj++){
            int job = tid + jj*256;
            int h=job>>8, d=(job>>4)&15, e=job&15;
            int ck=h*16+d, cq=h*16+e;
            float acc=0.f;
            #pragma unroll 8
            for(int p=0;p<64;p++) acc += sk[p*64+ck]*sq[p*64+cq];
            pS[job]+=acc;
        }
        if(tid<128){
            int c=tid&63;
            const float* s = (tid<64)? sq : sk;
            float acc=0.f;
            #pragma unroll 8
            for(int p=0;p<64;p++){ float v=s[p*64+c]; acc+=v*v; }
            pn[tid]+=acc;
        }
    }
    __syncthreads();
    float* gp = gpart + ((size_t)b*128 + blockIdx.x)*1152;
    for(int i=tid;i<1024;i+=256) gp[i]=pS[i];
    if(tid<128) gp[1024+tid]=pn[tid];
}

// ---------------- attn softmax + fold into Mcomb ---------------------------
__global__ __launch_bounds__(256) void k_attn(const float* __restrict__ gpart,
        const float* __restrict__ Wp, const float* __restrict__ resc,
        float* __restrict__ Mcomb){
    __shared__ float sred[2304];
    __shared__ float sa[2048];
    int tid = threadIdx.x;
    for(int jj=tid;jj<2304;jj+=256){
        int b=jj/1152, j=jj-b*1152;
        float acc=0.f;
        for(int blk=0;blk<128;blk++) acc += gpart[((size_t)b*128+blk)*1152 + j];
        sred[jj]=acc;
    }
    __syncthreads();
    if(tid<128){
        int b=tid>>6, hd=tid&63, h=hd>>4, d=hd&15;
        float nk = fmaxf(sqrtf(sred[b*1152+1088+hd]),1e-6f);
        float r = resc[h];
        float row[16]; float mx=-1e30f;
        #pragma unroll
        for(int e=0;e<16;e++){
            float nq = fmaxf(sqrtf(sred[b*1152+1024+h*16+e]),1e-6f);
            float v = sred[b*1152 + h*256 + d*16 + e] / (nk*nq) * r;
            row[e]=v; mx=fmaxf(mx,v);
        }
        float s=0.f;
        #pragma unroll
        for(int e=0;e<16;e++){ row[e]=expf(row[e]-mx); s+=row[e]; }
        float inv=1.f/s;
        #pragma unroll
        for(int e=0;e<16;e++) sa[((b*4+h)*16+d)*16+e] = row[e]*inv;
    }
    __syncthreads();
    for(int job=tid;job<8192;job+=256){
        int b=job>>12, rem=job&4095, ci=rem>>6, co=rem&63;
        int h=ci>>4, e=ci&15;
        float acc=0.f;
        #pragma unroll
        for(int d=0;d<16;d++) acc += sa[((b*4+h)*16+d)*16+e] * Wp[(h*16+d)*64+co];
        Mcomb[job]=acc;
    }
}

// ---------------- mask gate ------------------------------------------------
__global__ __launch_bounds__(256) void k_maskgate(const float* __restrict__ T,
        const float* __restrict__ M1, const float* __restrict__ V,
        const float* __restrict__ dw, const float* __restrict__ db,
        float* __restrict__ VG){
    __shared__ float sdw[1600];
    __shared__ float sdb[64];
    int tid=threadIdx.x;
    for(int i=tid;i<1600;i+=256) sdw[i]=dw[i];
    if(tid<64) sdb[tid]=db[tid];
    __syncthreads();
    size_t idx=(size_t)blockIdx.x*256+tid;
    int c=(int)(idx&63);
    size_t p=idx>>6;
    int b=(int)(p>>16);
    int pp=(int)(p&65535);
    int y=pp>>8, x=pp&255;
    float conv=0.f;
    #pragma unroll
    for(int dy=0;dy<5;dy++){
        int yy=y+dy-2; if(yy<0||yy>255) continue;
        #pragma unroll
        for(int dx=0;dx<5;dx++){
            int xx=x+dx-2; if(xx<0||xx>255) continue;
            conv += T[((((size_t)b<<16)+(yy<<8)+xx)<<6)+c]*sdw[(dy*5+dx)*64+c];
        }
    }
    float am = 1.f/(1.f+expf(-(conv+sdb[c])));
    VG[idx] = V[idx]*M1[idx]*(1.f+am);
}

// ---------------- depthwise 3x3 + GELU -------------------------------------
__global__ __launch_bounds__(256) void k_dw3_gelu(const float* __restrict__ in,
        const float* __restrict__ dw, float* __restrict__ out, int cbits){
    __shared__ float sdw[2304];
    int tid=threadIdx.x;
    int Cc=1<<cbits;
    for(int i=tid;i<9*Cc;i+=256) sdw[i]=dw[i];
    __syncthreads();
    size_t idx=(size_t)blockIdx.x*256+tid;
    int c=(int)(idx&(Cc-1));
    size_t p=idx>>cbits;
    int b=(int)(p>>16), pp=(int)(p&65535), y=pp>>8, x=pp&255;
    float conv=0.f;
    #pragma unroll
    for(int dy=0;dy<3;dy++){
        int yy=y+dy-1; if(yy<0||yy>255) continue;
        #pragma unroll
        for(int dx=0;dx<3;dx++){
            int xx=x+dx-1; if(xx<0||xx>255) continue;
            conv += in[((((size_t)b<<16)+(yy<<8)+xx)<<cbits)+c]*sdw[(dy*3+dx)*Cc+c];
        }
    }
    out[idx]=gelu_f(conv);
}

// ---------------- msa epilogue ---------------------------------------------
__global__ __launch_bounds__(256) void k_msa_out(const float* __restrict__ OC,
        const float* __restrict__ P, const float* __restrict__ pe2,
        float* __restrict__ X){
    __shared__ float sdw[576];
    int tid=threadIdx.x;
    for(int i=tid;i<576;i+=256) sdw[i]=pe2[i];
    __syncthreads();
    size_t idx=(size_t)blockIdx.x*256+tid;
    int c=(int)(idx&63);
    size_t p=idx>>6;
    int b=(int)(p>>16), pp=(int)(p&65535), y=pp>>8, x=pp&255;
    float conv=0.f;
    #pragma unroll
    for(int dy=0;dy<3;dy++){
        int yy=y+dy-1; if(yy<0||yy>255) continue;
        #pragma unroll
        for(int dx=0;dx<3;dx++){
            int xx=x+dx-1; if(xx<0||xx>255) continue;
            conv += P[((((size_t)b<<16)+(yy<<8)+xx)<<6)+c]*sdw[(dy*3+dx)*64+c];
        }
    }
    X[idx] += OC[idx] + conv;
}

// ---------------- host -----------------------------------------------------
extern "C" void kernel_launch(void* const* d_in, const int* in_sizes, int n_in,
                              void* d_out, int out_size){
    const float* x    = (const float*)d_in[0];
    const float* mask = (const float*)d_in[1];
    const float* Wq   = (const float*)d_in[2];
    const float* Wk   = (const float*)d_in[3];
    const float* Wv   = (const float*)d_in[4];
    const float* resc = (const float*)d_in[5];
    const float* Wp   = (const float*)d_in[6];
    const float* bp   = (const float*)d_in[7];
    const float* pe1  = (const float*)d_in[8];
    const float* pe2  = (const float*)d_in[9];
    const float* mw1  = (const float*)d_in[10];
    const float* mb1  = (const float*)d_in[11];
    const float* mw2  = (const float*)d_in[12];
    const float* mb2  = (const float*)d_in[13];
    const float* mdw  = (const float*)d_in[14];
    const float* mdb  = (const float*)d_in[15];
    const float* lng  = (const float*)d_in[16];
    const float* lnb  = (const float*)d_in[17];
    const float* fw1  = (const float*)d_in[18];
    const float* fdw  = (const float*)d_in[19];
    const float* fw2  = (const float*)d_in[20];
    float* out = (float*)d_out;

    float *pX,*pM,*pQ,*pK,*pV,*pT1,*pT2,*pH1,*pH2,*pGP,*pMC;
    cudaGetSymbolAddress((void**)&pX,  g_X);
    cudaGetSymbolAddress((void**)&pM,  g_Mk);
    cudaGetSymbolAddress((void**)&pQ,  g_Q);
    cudaGetSymbolAddress((void**)&pK,  g_K);
    cudaGetSymbolAddress((void**)&pV,  g_V);
    cudaGetSymbolAddress((void**)&pT1, g_T1);
    cudaGetSymbolAddress((void**)&pT2, g_T2);
    cudaGetSymbolAddress((void**)&pH1, g_H1);
    cudaGetSymbolAddress((void**)&pH2, g_H2);
    cudaGetSymbolAddress((void**)&pGP, g_GP);
    cudaGetSymbolAddress((void**)&pMC, g_MC);

    cudaFuncSetAttribute(k_gemm<1,0>, cudaFuncAttributeMaxDynamicSharedMemorySize, GSM_BYTES);
    cudaFuncSetAttribute(k_gemm<1,1>, cudaFuncAttributeMaxDynamicSharedMemorySize, GSM_BYTES);
    cudaFuncSetAttribute(k_gemm<4,2>, cudaFuncAttributeMaxDynamicSharedMemorySize, GSM_BYTES);

    dim3 tg(2048,2,2);
    k_nchw2nhwc<<<tg,256>>>(x,    pX);
    k_nchw2nhwc<<<tg,256>>>(mask, pM);

    for(int i=0;i<3;i++){
        const float* Wq_i  = Wq  + i*4096;
        const float* Wk_i  = Wk  + i*4096;
        const float* Wv_i  = Wv  + i*4096;
        const float* Wp_i  = Wp  + i*4096;
        const float* mw1_i = mw1 + i*4096;
        const float* mw2_i = mw2 + i*4096;
        const float* bp_i  = bp  + i*64;
        const float* mb1_i = mb1 + i*64;
        const float* mb2_i = mb2 + i*64;
        const float* mdb_i = mdb + i*64;
        const float* lng_i = lng + i*64;
        const float* lnb_i = lnb + i*64;
        const float* pe1_i = pe1 + i*576;
        const float* pe2_i = pe2 + i*576;
        const float* mdw_i = mdw + i*1600;
        const float* rs_i  = resc+ i*4;
        const float* fw1_i = fw1 + i*64*256;
        const float* fdw_i = fdw + i*9*256;
        const float* fw2_i = fw2 + i*256*64;

        // attention stats path
        k_gemm<1,0><<<512,128,GSM_BYTES>>>(pX, 64, Wq_i, 64, 0, nullptr, pQ, 64);
        k_gemm<1,0><<<512,128,GSM_BYTES>>>(pX, 64, Wk_i, 64, 0, nullptr, pK, 64);
        k_gram<<<dim3(128,2),256>>>(pQ, pK, pGP);
        k_attn<<<1,256>>>(pGP, Wp_i, rs_i, pMC);
        // v + mask gate
        k_gemm<1,0><<<512,128,GSM_BYTES>>>(pX, 64, Wv_i, 64, 0, nullptr, pV, 64);
        k_gemm<1,0><<<512,128,GSM_BYTES>>>(pM, 64, mw1_i, 64, 0, mb1_i, pT1, 64);
        k_gemm<1,0><<<512,128,GSM_BYTES>>>(pT1, 64, mw2_i, 64, 0, mb2_i, pT2, 64);
        k_maskgate<<<32768,256>>>(pT2, pT1, pV, mdw_i, mdb_i, pQ);   // VG -> g_Q
        // positional path
        k_dw3_gelu<<<32768,256>>>(pV, pe1_i, pK, 6);                 // P -> g_K
        // attention apply + proj (folded)
        k_gemm<1,0><<<512,128,GSM_BYTES>>>(pQ, 64, pMC, 64, 4096, bp_i, pT2, 64); // OC -> g_T2
        k_msa_out<<<32768,256>>>(pT2, pK, pe2_i, pX);                // X += OC + dw3(P)
        // feed-forward
        k_ln<<<1024,256>>>(pX, lng_i, lnb_i, pT1);
        k_gemm<1,1><<<dim3(512,4),128,GSM_BYTES>>>(pT1, 64, fw1_i, 256, 0, nullptr, pH1, 256);
        k_dw3_gelu<<<131072,256>>>(pH1, fdw_i, pH2, 8);
        k_gemm<4,2><<<512,128,GSM_BYTES>>>(pH2, 256, fw2_i, 64, 0, nullptr, pX, 64);
    }

    k_nhwc2nchw<<<tg,256>>>(pX, out);
}

// round 3
// speedup vs baseline: 2.0071x; 1.5266x over previous
#include <cuda_runtime.h>
#include <math.h>

#define NPB 65536
#define NT  131072
typedef unsigned long long ull;

// ---------------- scratch ----------
__device__ float g_X [NT*64];
__device__ float g_Mk[NT*64];
__device__ float g_Q [NT*64];
__device__ float g_K [NT*64];
__device__ float g_V [NT*64];
__device__ float g_T1[NT*64];
__device__ float g_H1[NT*256];
__device__ float g_H2[NT*256];
__device__ float g_GP[2*128*1152];
__device__ float g_MC[2*64*64];

__device__ __forceinline__ float gelu_f(float u){
    return 0.5f*u*(1.f+erff(u*0.70710678118654752f));
}
__device__ __forceinline__ ull pk2(float lo, float hi){
    ull r; asm("mov.b64 %0, {%1,%2};" : "=l"(r) : "f"(lo), "f"(hi)); return r;
}
__device__ __forceinline__ void upk2(ull v, float&lo, float&hi){
    asm("mov.b64 {%0,%1}, %2;" : "=f"(lo), "=f"(hi) : "l"(v));
}
#define FMA2(acc, a, b) asm("fma.rn.f32x2 %0, %1, %2, %0;" : "+l"(acc) : "l"(a), "l"(b))

// ---------------- transposes ----------------
__global__ __launch_bounds__(256) void k_nchw2nhwc(const float* __restrict__ in, float* __restrict__ out){
    __shared__ float t[32][33];
    int tx = threadIdx.x & 31, ty = threadIdx.x >> 5;
    int pt = blockIdx.x, ct = blockIdx.y, b = blockIdx.z;
    const float* ip = in  + (size_t)b*64*NPB;
    float*       op = out + (size_t)b*NPB*64;
    #pragma unroll
    for(int r=0;r<4;r++){
        int c = ct*32 + ty + r*8;
        t[ty+r*8][tx] = ip[(size_t)c*NPB + (size_t)pt*32 + tx];
    }
    __syncthreads();
    #pragma unroll
    for(int r=0;r<4;r++){
        int p = pt*32 + ty + r*8;
        op[(size_t)p*64 + ct*32 + tx] = t[tx][ty+r*8];
    }
}
__global__ __launch_bounds__(256) void k_nhwc2nchw(const float* __restrict__ in, float* __restrict__ out){
    __shared__ float t[32][33];
    int tx = threadIdx.x & 31, ty = threadIdx.x >> 5;
    int pt = blockIdx.x, ct = blockIdx.y, b = blockIdx.z;
    const float* ip = in  + (size_t)b*NPB*64;
    float*       op = out + (size_t)b*64*NPB;
    #pragma unroll
    for(int r=0;r<4;r++){
        int p = pt*32 + ty + r*8;
        t[ty+r*8][tx] = ip[(size_t)p*64 + ct*32 + tx];
    }
    __syncthreads();
    #pragma unroll
    for(int r=0;r<4;r++){
        int c = ct*32 + ty + r*8;
        op[(size_t)c*NPB + (size_t)pt*32 + tx] = t[tx][ty+r*8];
    }
}

// ---------------- FFMA2 GEMM, occupancy-tuned ------------------------------
// Tile: 128 px x 64 outs, 128 threads, 4 blocks/SM.
// Thread (og=t>>4 in 0..7, pg=t&15): outs [og*8,og*8+8) as 4 out-pairs,
// pixels pg+16*i for i in 0..7. acc[i*4+kp] = f32x2 over (out 2kp, 2kp+1).
// Weights staged as natural float2 pairs (ull). X staged [ch][px], stride 129.
// MODE: 0 store, 1 gelu+store, 2 add-to-OUT.
#define XS_FLOATS (64*129)
#define GSM_BYTES (XS_FLOATS*4 + 64*32*8)

template<int IN_CHUNKS, int MODE>
__global__ __launch_bounds__(128, 4) void k_gemm(
        const float* __restrict__ X, int xStride,
        const float* __restrict__ W, int wStride, int wBatchStride,
        const float* __restrict__ bias,
        float* __restrict__ OUT, int oStride){
    extern __shared__ char smraw[];
    float* xs = (float*)smraw;
    ull*   wd = (ull*)(smraw + XS_FLOATS*4);
    const int t = threadIdx.x;
    const int og = t >> 4, pg = t & 15;
    const size_t tileBase = (size_t)blockIdx.x * 128;
    const int coOff = blockIdx.y * 64;
    const float* Wb = W + (wBatchStride ? (int)(tileBase >> 16) * (size_t)wBatchStride : 0);

    ull acc[32];
    if(bias){
        #pragma unroll
        for(int kp=0;kp<4;kp++){
            ull b2 = pk2(bias[og*8+2*kp], bias[og*8+2*kp+1]);
            #pragma unroll
            for(int i=0;i<8;i++) acc[i*4+kp] = b2;
        }
    } else {
        #pragma unroll
        for(int q=0;q<32;q++) acc[q] = 0ull;
    }

    for(int jc=0;jc<IN_CHUNKS;jc++){
        if(jc) __syncthreads();
        // stage weights: wd[j*32+kp] = (W[row,coOff+2kp], W[row,coOff+2kp+1])
        #pragma unroll
        for(int r=0;r<16;r++){
            int s = t + r*128;
            int j = s >> 5, kp = s & 31;
            wd[s] = *(const ull*)(Wb + (size_t)(jc*64 + j)*wStride + coOff + 2*kp);
        }
        // stage X tile transposed: xs[j*129 + p]
        #pragma unroll
        for(int r=0;r<32;r++){
            int s = t + r*128;
            int p = s >> 5, j2 = s & 31;
            float2 v = *(const float2*)(X + (tileBase+p)*xStride + jc*64 + j2*2);
            xs[(j2*2  )*129 + p] = v.x;
            xs[(j2*2+1)*129 + p] = v.y;
        }
        __syncthreads();
        for(int j=0;j<64;j++){
            ull wv[4];
            const ull* wr = wd + j*32 + og*4;
            #pragma unroll
            for(int kp=0;kp<4;kp++) wv[kp] = wr[kp];
            const float* xr = xs + j*129 + pg;
            #pragma unroll
            for(int i=0;i<8;i++){
                float xv = xr[16*i];
                ull x2 = pk2(xv, xv);
                #pragma unroll
                for(int kp=0;kp<4;kp++)
                    FMA2(acc[i*4+kp], x2, wv[kp]);
            }
        }
    }
    // epilogue
    #pragma unroll
    for(int i=0;i<8;i++){
        size_t p = tileBase + pg + 16*i;
        float v[8];
        #pragma unroll
        for(int kp=0;kp<4;kp++) upk2(acc[i*4+kp], v[2*kp], v[2*kp+1]);
        if(MODE==1){
            #pragma unroll
            for(int k=0;k<8;k++) v[k] = gelu_f(v[k]);
        }
        float* o = OUT + p*oStride + coOff + og*8;
        if(MODE==2){
            float4 a = *(float4*)o, b = *(float4*)(o+4);
            v[0]+=a.x; v[1]+=a.y; v[2]+=a.z; v[3]+=a.w;
            v[4]+=b.x; v[5]+=b.y; v[6]+=b.z; v[7]+=b.w;
        }
        *(float4*)(o)   = make_float4(v[0],v[1],v[2],v[3]);
        *(float4*)(o+4) = make_float4(v[4],v[5],v[6],v[7]);
    }
}

// ---------------- coalesced LayerNorm --------------------------------------
__global__ __launch_bounds__(256) void k_ln(const float* __restrict__ X,
        const float* __restrict__ g, const float* __restrict__ b,
        float* __restrict__ O){
    __shared__ float sx[128*66];
    __shared__ float smu[128], srs[128];
    int t = threadIdx.x;
    size_t base = (size_t)blockIdx.x * 128;
    for(int s=t;s<4096;s+=256){
        int p = s >> 5, j2 = s & 31;
        float2 v = *(const float2*)(X + (base+p)*64 + j2*2);
        sx[p*66 + j2*2]   = v.x;
        sx[p*66 + j2*2+1] = v.y;
    }
    __syncthreads();
    if(t<128){
        float mu=0.f, m2=0.f;
        const float* r = sx + t*66;
        #pragma unroll 8
        for(int j=0;j<64;j++){ float v=r[j]; mu+=v; m2+=v*v; }
        mu *= (1.f/64.f);
        float var = fmaxf(m2*(1.f/64.f) - mu*mu, 0.f);
        smu[t]=mu; srs[t]=rsqrtf(var+1e-5f);
    }
    __syncthreads();
    for(int s=t;s<4096;s+=256){
        int p = s >> 5, j2 = s & 31;
        float mu=smu[p], rs=srs[p];
        int j = j2*2;
        float2 v;
        v.x = (sx[p*66+j]  -mu)*rs*g[j]  +b[j];
        v.y = (sx[p*66+j+1]-mu)*rs*g[j+1]+b[j+1];
        *(float2*)(O + (base+p)*64 + j) = v;
    }
}

// ---------------- gram partials --------------------------------------------
__global__ __launch_bounds__(256) void k_gram(const float* __restrict__ Q,
        const float* __restrict__ K, float* __restrict__ gpart){
    __shared__ float sq[4096], sk[4096];
    __shared__ float pS[1024];
    __shared__ float pn[128];
    int tid = threadIdx.x;
    int b = blockIdx.y;
    for(int i=tid;i<1024;i+=256) pS[i]=0.f;
    if(tid<128) pn[tid]=0.f;
    for(int t=0;t<8;t++){
        size_t base = ((size_t)b*NPB + (size_t)blockIdx.x*512 + t*64)*64;
        __syncthreads();
        for(int i=tid;i<4096;i+=256){ sq[i]=Q[base+i]; sk[i]=K[base+i]; }
        __syncthreads();
        #pragma unroll
        for(int jj=0;jj<4;jj++){
            int job = tid + jj*256;
            int h=job>>8, d=(job>>4)&15, e=job&15;
            int ck=h*16+d, cq=h*16+e;
            float acc=0.f;
            #pragma unroll 8
            for(int p=0;p<64;p++) acc += sk[p*64+ck]*sq[p*64+cq];
            pS[job]+=acc;
        }
        if(tid<128){
            int c=tid&63;
            const float* s = (tid<64)? sq : sk;
            float acc=0.f;
            #pragma unroll 8
            for(int p=0;p<64;p++){ float v=s[p*64+c]; acc+=v*v; }
            pn[tid]+=acc;
        }
    }
    __syncthreads();
    float* gp = gpart + ((size_t)b*128 + blockIdx.x)*1152;
    for(int i=tid;i<1024;i+=256) gp[i]=pS[i];
    if(tid<128) gp[1024+tid]=pn[tid];
}

// ---------------- attn softmax + fold into Mcomb ---------------------------
__global__ __launch_bounds__(256) void k_attn(const float* __restrict__ gpart,
        const float* __restrict__ Wp, const float* __restrict__ resc,
        float* __restrict__ Mcomb){
    __shared__ float sred[2304];
    __shared__ float sa[2048];
    int tid = threadIdx.x;
    for(int jj=tid;jj<2304;jj+=256){
        int b=jj/1152, j=jj-b*1152;
        float acc=0.f;
        for(int blk=0;blk<128;blk++) acc += gpart[((size_t)b*128+blk)*1152 + j];
        sred[jj]=acc;
    }
    __syncthreads();
    if(tid<128){
        int b=tid>>6, hd=tid&63, h=hd>>4, d=hd&15;
        float nk = fmaxf(sqrtf(sred[b*1152+1088+hd]),1e-6f);
        float r = resc[h];
        float row[16]; float mx=-1e30f;
        #pragma unroll
        for(int e=0;e<16;e++){
            float nq = fmaxf(sqrtf(sred[b*1152+1024+h*16+e]),1e-6f);
            float v = sred[b*1152 + h*256 + d*16 + e] / (nk*nq) * r;
            row[e]=v; mx=fmaxf(mx,v);
        }
        float s=0.f;
        #pragma unroll
        for(int e=0;e<16;e++){ row[e]=expf(row[e]-mx); s+=row[e]; }
        float inv=1.f/s;
        #pragma unroll
        for(int e=0;e<16;e++) sa[((b*4+h)*16+d)*16+e] = row[e]*inv;
    }
    __syncthreads();
    for(int job=tid;job<8192;job+=256){
        int b=job>>12, rem=job&4095, ci=rem>>6, co=rem&63;
        int h=ci>>4, e=ci&15;
        float acc=0.f;
        #pragma unroll
        for(int d=0;d<16;d++) acc += sa[((b*4+h)*16+d)*16+e] * Wp[(h*16+d)*64+co];
        Mcomb[job]=acc;
    }
}

// ---------------- mask gate (float4) ---------------------------------------
__global__ __launch_bounds__(256) void k_maskgate(const float* __restrict__ T,
        const float* __restrict__ M1, const float* __restrict__ V,
        const float* __restrict__ dw, const float* __restrict__ db,
        float* __restrict__ VG){
    __shared__ float4 sdw[400];
    __shared__ float4 sdb4[16];
    int tid=threadIdx.x;
    for(int i=tid;i<400;i+=256) sdw[i]=((const float4*)dw)[i];
    if(tid<16) sdb4[tid]=((const float4*)db)[tid];
    __syncthreads();
    size_t e=(size_t)blockIdx.x*256+tid;
    int c4=(int)(e&15);
    size_t p=e>>4;
    int b=(int)(p>>16);
    int pp=(int)(p&65535);
    int y=pp>>8, x=pp&255;
    float4 conv=make_float4(0,0,0,0);
    #pragma unroll
    for(int dy=0;dy<5;dy++){
        int yy=y+dy-2; if(yy<0||yy>255) continue;
        #pragma unroll
        for(int dx=0;dx<5;dx++){
            int xx=x+dx-2; if(xx<0||xx>255) continue;
            float4 tv = *(const float4*)(T + (((((size_t)b<<16)+(yy<<8)+xx)<<6)+c4*4));
            float4 wv = sdw[(dy*5+dx)*16+c4];
            conv.x+=tv.x*wv.x; conv.y+=tv.y*wv.y; conv.z+=tv.z*wv.z; conv.w+=tv.w*wv.w;
        }
    }
    float4 bb=sdb4[c4];
    float4 m1=((const float4*)M1)[e];
    float4 vv=((const float4*)V)[e];
    float4 r;
    r.x = vv.x*m1.x*(1.f+1.f/(1.f+expf(-(conv.x+bb.x))));
    r.y = vv.y*m1.y*(1.f+1.f/(1.f+expf(-(conv.y+bb.y))));
    r.z = vv.z*m1.z*(1.f+1.f/(1.f+expf(-(conv.z+bb.z))));
    r.w = vv.w*m1.w*(1.f+1.f/(1.f+expf(-(conv.w+bb.w))));
    ((float4*)VG)[e]=r;
}

// ---------------- depthwise 3x3 + GELU (float4) ----------------------------
__global__ __launch_bounds__(256) void k_dw3_gelu(const float* __restrict__ in,
        const float* __restrict__ dw, float* __restrict__ out, int cbits){
    __shared__ float4 sdw[576];
    int tid=threadIdx.x;
    int C4=1<<(cbits-2);
    for(int i=tid;i<9*C4;i+=256) sdw[i]=((const float4*)dw)[i];
    __syncthreads();
    size_t e=(size_t)blockIdx.x*256+tid;
    int c4=(int)(e&(C4-1));
    size_t p=e>>(cbits-2);
    int b=(int)(p>>16), pp=(int)(p&65535), y=pp>>8, x=pp&255;
    float4 conv=make_float4(0,0,0,0);
    #pragma unroll
    for(int dy=0;dy<3;dy++){
        int yy=y+dy-1; if(yy<0||yy>255) continue;
        #pragma unroll
        for(int dx=0;dx<3;dx++){
            int xx=x+dx-1; if(xx<0||xx>255) continue;
            float4 tv = *(const float4*)(in + ((((((size_t)b<<16)+(yy<<8)+xx))<<cbits)+c4*4));
            float4 wv = sdw[(dy*3+dx)*C4+c4];
            conv.x+=tv.x*wv.x; conv.y+=tv.y*wv.y; conv.z+=tv.z*wv.z; conv.w+=tv.w*wv.w;
        }
    }
    float4 r=make_float4(gelu_f(conv.x),gelu_f(conv.y),gelu_f(conv.z),gelu_f(conv.w));
    ((float4*)out)[e]=r;
}

// ---------------- msa epilogue: X += dw3(P, pe2) (float4) ------------------
__global__ __launch_bounds__(256) void k_msa_out(
        const float* __restrict__ P, const float* __restrict__ pe2,
        float* __restrict__ X){
    __shared__ float4 sdw[144];
    int tid=threadIdx.x;
    if(tid<144) sdw[tid]=((const float4*)pe2)[tid];
    __syncthreads();
    size_t e=(size_t)blockIdx.x*256+tid;
    int c4=(int)(e&15);
    size_t p=e>>4;
    int b=(int)(p>>16), pp=(int)(p&65535), y=pp>>8, x=pp&255;
    float4 conv=make_float4(0,0,0,0);
    #pragma unroll
    for(int dy=0;dy<3;dy++){
        int yy=y+dy-1; if(yy<0||yy>255) continue;
        #pragma unroll
        for(int dx=0;dx<3;dx++){
            int xx=x+dx-1; if(xx<0||xx>255) continue;
            float4 tv = *(const float4*)(P + (((((size_t)b<<16)+(yy<<8)+xx)<<6)+c4*4));
            float4 wv = sdw[(dy*3+dx)*16+c4];
            conv.x+=tv.x*wv.x; conv.y+=tv.y*wv.y; conv.z+=tv.z*wv.z; conv.w+=tv.w*wv.w;
        }
    }
    float4 xv=((float4*)X)[e];
    xv.x+=conv.x; xv.y+=conv.y; xv.z+=conv.z; xv.w+=conv.w;
    ((float4*)X)[e]=xv;
}

// ---------------- host -----------------------------------------------------
extern "C" void kernel_launch(void* const* d_in, const int* in_sizes, int n_in,
                              void* d_out, int out_size){
    const float* x    = (const float*)d_in[0];
    const float* mask = (const float*)d_in[1];
    const float* Wq   = (const float*)d_in[2];
    const float* Wk   = (const float*)d_in[3];
    const float* Wv   = (const float*)d_in[4];
    const float* resc = (const float*)d_in[5];
    const float* Wp   = (const float*)d_in[6];
    const float* bp   = (const float*)d_in[7];
    const float* pe1  = (const float*)d_in[8];
    const float* pe2  = (const float*)d_in[9];
    const float* mw1  = (const float*)d_in[10];
    const float* mb1  = (const float*)d_in[11];
    const float* mw2  = (const float*)d_in[12];
    const float* mb2  = (const float*)d_in[13];
    const float* mdw  = (const float*)d_in[14];
    const float* mdb  = (const float*)d_in[15];
    const float* lng  = (const float*)d_in[16];
    const float* lnb  = (const float*)d_in[17];
    const float* fw1  = (const float*)d_in[18];
    const float* fdw  = (const float*)d_in[19];
    const float* fw2  = (const float*)d_in[20];
    float* out = (float*)d_out;

    float *pX,*pM,*pQ,*pK,*pV,*pT1,*pH1,*pH2,*pGP,*pMC;
    cudaGetSymbolAddress((void**)&pX,  g_X);
    cudaGetSymbolAddress((void**)&pM,  g_Mk);
    cudaGetSymbolAddress((void**)&pQ,  g_Q);
    cudaGetSymbolAddress((void**)&pK,  g_K);
    cudaGetSymbolAddress((void**)&pV,  g_V);
    cudaGetSymbolAddress((void**)&pT1, g_T1);
    cudaGetSymbolAddress((void**)&pH1, g_H1);
    cudaGetSymbolAddress((void**)&pH2, g_H2);
    cudaGetSymbolAddress((void**)&pGP, g_GP);
    cudaGetSymbolAddress((void**)&pMC, g_MC);

    cudaFuncSetAttribute(k_gemm<1,0>, cudaFuncAttributeMaxDynamicSharedMemorySize, GSM_BYTES);
    cudaFuncSetAttribute(k_gemm<1,1>, cudaFuncAttributeMaxDynamicSharedMemorySize, GSM_BYTES);
    cudaFuncSetAttribute(k_gemm<1,2>, cudaFuncAttributeMaxDynamicSharedMemorySize, GSM_BYTES);
    cudaFuncSetAttribute(k_gemm<4,2>, cudaFuncAttributeMaxDynamicSharedMemorySize, GSM_BYTES);

    dim3 tg(2048,2,2);
    k_nchw2nhwc<<<tg,256>>>(x,    pX);
    k_nchw2nhwc<<<tg,256>>>(mask, pM);

    for(int i=0;i<3;i++){
        const float* Wq_i  = Wq  + i*4096;
        const float* Wk_i  = Wk  + i*4096;
        const float* Wv_i  = Wv  + i*4096;
        const float* Wp_i  = Wp  + i*4096;
        const float* mw1_i = mw1 + i*4096;
        const float* mw2_i = mw2 + i*4096;
        const float* bp_i  = bp  + i*64;
        const float* mb1_i = mb1 + i*64;
        const float* mb2_i = mb2 + i*64;
        const float* mdb_i = mdb + i*64;
        const float* lng_i = lng + i*64;
        const float* lnb_i = lnb + i*64;
        const float* pe1_i = pe1 + i*576;
        const float* pe2_i = pe2 + i*576;
        const float* mdw_i = mdw + i*1600;
        const float* rs_i  = resc+ i*4;
        const float* fw1_i = fw1 + i*64*256;
        const float* fdw_i = fdw + i*9*256;
        const float* fw2_i = fw2 + i*256*64;

        // attention stats path
        k_gemm<1,0><<<1024,128,GSM_BYTES>>>(pX, 64, Wq_i, 64, 0, nullptr, pQ, 64);
        k_gemm<1,0><<<1024,128,GSM_BYTES>>>(pX, 64, Wk_i, 64, 0, nullptr, pK, 64);
        k_gram<<<dim3(128,2),256>>>(pQ, pK, pGP);
        k_attn<<<1,256>>>(pGP, Wp_i, rs_i, pMC);
        // v + mask gate
        k_gemm<1,0><<<1024,128,GSM_BYTES>>>(pX, 64, Wv_i, 64, 0, nullptr, pV, 64);
        k_gemm<1,0><<<1024,128,GSM_BYTES>>>(pM, 64, mw1_i, 64, 0, mb1_i, pT1, 64);
        k_gemm<1,0><<<1024,128,GSM_BYTES>>>(pT1, 64, mw2_i, 64, 0, mb2_i, pQ, 64);
        k_maskgate<<<8192,256>>>(pQ, pT1, pV, mdw_i, mdb_i, pT1);    // VG -> g_T1
        // positional path
        k_dw3_gelu<<<8192,256>>>(pV, pe1_i, pK, 6);                  // P -> g_K
        // folded attention apply + proj, added straight into X
        k_gemm<1,2><<<1024,128,GSM_BYTES>>>(pT1, 64, pMC, 64, 4096, bp_i, pX, 64);
        k_msa_out<<<8192,256>>>(pK, pe2_i, pX);                      // X += dw3(P)
        // feed-forward
        k_ln<<<1024,256>>>(pX, lng_i, lnb_i, pT1);
        k_gemm<1,1><<<dim3(1024,4),128,GSM_BYTES>>>(pT1, 64, fw1_i, 256, 0, nullptr, pH1, 256);
        k_dw3_gelu<<<32768,256>>>(pH1, fdw_i, pH2, 8);
        k_gemm<4,2><<<1024,128,GSM_BYTES>>>(pH2, 256, fw2_i, 64, 0, nullptr, pX, 64);
    }

    k_nhwc2nchw<<<tg,256>>>(pX, out);
}

// round 7
// speedup vs baseline: 2.7531x; 1.3717x over previous
#include <cuda_runtime.h>
#include <math.h>
#include <stdint.h>

#define NPB 65536
#define NT  131072

// ---------------- scratch ----------
__device__ float g_X [NT*64];
__device__ float g_Mk[NT*64];
__device__ float g_Q [NT*64];
__device__ float g_K [NT*64];
__device__ float g_V [NT*64];
__device__ float g_T1[NT*64];
__device__ float g_H1[NT*256];
__device__ float g_H2[NT*256];
__device__ float g_GP[2*128*1152];
__device__ float g_MC[2*64*64];

__device__ __forceinline__ float gelu_f(float u){
    return 0.5f*u*(1.f+erff(u*0.70710678118654752f));
}
__device__ __forceinline__ uint32_t tf32c(float f){
    uint32_t r; asm("cvt.rna.tf32.f32 %0, %1;" : "=r"(r) : "f"(f)); return r;
}
#define MMA_TF32(d, a, b0, b1) \
  asm volatile("mma.sync.aligned.m16n8k8.row.col.f32.tf32.tf32.f32 " \
    "{%0,%1,%2,%3},{%4,%5,%6,%7},{%8,%9},{%0,%1,%2,%3};" \
    : "+f"((d)[0]),"+f"((d)[1]),"+f"((d)[2]),"+f"((d)[3]) \
    : "r"((a)[0]),"r"((a)[1]),"r"((a)[2]),"r"((a)[3]),"r"(b0),"r"(b1))

// ---------------- tf32 tensor GEMM -----------------------------------------
// Tile 128px(M) x 64out(N), K=64 per chunk. 128 threads = 4 warps.
// Warp w owns px rows [w*32, w*32+32) as 2 m16 tiles; 8 n8 tiles; 8 k-steps.
// KC: K chunks (acc persists). NC: N chunks (re-stage W, epilogue per chunk).
// MODE: 0 store, 1 gelu+store, 2 add-to-OUT.
#define XS_STRIDE 68
#define WS_STRIDE 72
#define XS_U (128*XS_STRIDE)
#define WS_U (64*WS_STRIDE)
#define TM_SMEM ((XS_U + WS_U + 64)*4)

template<int KC,int NC,int MODE>
__global__ __launch_bounds__(128, 4) void k_tmma(
        const float* __restrict__ X, int xStride,
        const float* __restrict__ W, int wStride, int wBatchStride,
        const float* __restrict__ bias,
        float* __restrict__ OUT, int oStride){
    extern __shared__ uint32_t smu[];
    uint32_t* xs = smu;
    uint32_t* ws = smu + XS_U;
    float*    sb = (float*)(smu + XS_U + WS_U);
    const int t = threadIdx.x;
    const int warp = t>>5, lane = t&31;
    const int lr = lane>>2, lc = lane&3;
    const int m0 = warp*32;
    const size_t tileBase = (size_t)blockIdx.x*128;
    const float* Wb = W + (wBatchStride ? (int)(tileBase>>16)*(size_t)wBatchStride : 0);
    if(bias && t<64) sb[t] = bias[t];

    float acc[64];
    const int CH = (KC>NC)?KC:NC;

    for(int c=0;c<CH;c++){
        const int kOff = (KC>1)? c*64 : 0;
        const int nOff = (NC>1)? c*64 : 0;
        if(c) __syncthreads();
        if(c==0 || KC>1){
            #pragma unroll
            for(int it=0;it<16;it++){
                int s4 = t + it*128;
                int p = s4>>4, c4 = s4&15;
                float4 v = *(const float4*)(X + (tileBase+p)*(size_t)xStride + kOff + c4*4);
                uint32_t* xr = xs + p*XS_STRIDE + c4*4;
                xr[0]=tf32c(v.x); xr[1]=tf32c(v.y); xr[2]=tf32c(v.z); xr[3]=tf32c(v.w);
            }
        }
        #pragma unroll
        for(int it=0;it<32;it++){
            int s = t + it*128;
            int o = s&63, j = s>>6;
            ws[j*WS_STRIDE+o] = tf32c(Wb[(size_t)(kOff+j)*wStride + nOff + o]);
        }
        __syncthreads();
        if(c==0 || NC>1){
            if(bias){
                #pragma unroll
                for(int mt=0;mt<2;mt++)
                    #pragma unroll
                    for(int j=0;j<8;j++){
                        float b0 = sb[j*8 + 2*lc], b1 = sb[j*8 + 2*lc + 1];
                        acc[mt*32+j*4+0]=b0; acc[mt*32+j*4+1]=b1;
                        acc[mt*32+j*4+2]=b0; acc[mt*32+j*4+3]=b1;
                    }
            } else {
                #pragma unroll
                for(int q=0;q<64;q++) acc[q]=0.f;
            }
        }
        #pragma unroll
        for(int k0=0;k0<64;k0+=8){
            uint32_t a[2][4];
            #pragma unroll
            for(int mt=0;mt<2;mt++){
                const uint32_t* xb = xs + (m0+mt*16+lr)*XS_STRIDE + k0 + lc;
                a[mt][0]=xb[0]; a[mt][1]=xb[8*XS_STRIDE];
                a[mt][2]=xb[4]; a[mt][3]=xb[8*XS_STRIDE+4];
            }
            #pragma unroll
            for(int j=0;j<8;j++){
                uint32_t b0 = ws[(k0+lc  )*WS_STRIDE + j*8 + lr];
                uint32_t b1 = ws[(k0+lc+4)*WS_STRIDE + j*8 + lr];
                MMA_TF32(acc +      j*4, a[0], b0, b1);
                MMA_TF32(acc + 32 + j*4, a[1], b0, b1);
            }
        }
        if(NC>1 || c==CH-1){
            // epilogue
            #pragma unroll
            for(int mt=0;mt<2;mt++){
                #pragma unroll
                for(int j=0;j<8;j++){
                    size_t row = tileBase + m0 + mt*16 + lr;
                    int col = nOff + j*8 + 2*lc;
                    float v0=acc[mt*32+j*4], v1=acc[mt*32+j*4+1];
                    float v2=acc[mt*32+j*4+2], v3=acc[mt*32+j*4+3];
                    if(MODE==1){ v0=gelu_f(v0); v1=gelu_f(v1); v2=gelu_f(v2); v3=gelu_f(v3); }
                    float* p0 = OUT + row*(size_t)oStride + col;
                    float* p8 = p0 + 8*(size_t)oStride;
                    if(MODE==2){
                        float2 o0 = *(float2*)p0, o8 = *(float2*)p8;
                        v0+=o0.x; v1+=o0.y; v2+=o8.x; v3+=o8.y;
                    }
                    *(float2*)p0 = make_float2(v0,v1);
                    *(float2*)p8 = make_float2(v2,v3);
                }
            }
        }
    }
}

// ---------------- transposes ----------------
__global__ __launch_bounds__(256) void k_nchw2nhwc(const float* __restrict__ in, float* __restrict__ out){
    __shared__ float t[32][33];
    int tx = threadIdx.x & 31, ty = threadIdx.x >> 5;
    int pt = blockIdx.x, ct = blockIdx.y, b = blockIdx.z;
    const float* ip = in  + (size_t)b*64*NPB;
    float*       op = out + (size_t)b*NPB*64;
    #pragma unroll
    for(int r=0;r<4;r++){
        int c = ct*32 + ty + r*8;
        t[ty+r*8][tx] = ip[(size_t)c*NPB + (size_t)pt*32 + tx];
    }
    __syncthreads();
    #pragma unroll
    for(int r=0;r<4;r++){
        int p = pt*32 + ty + r*8;
        op[(size_t)p*64 + ct*32 + tx] = t[tx][ty+r*8];
    }
}
__global__ __launch_bounds__(256) void k_nhwc2nchw(const float* __restrict__ in, float* __restrict__ out){
    __shared__ float t[32][33];
    int tx = threadIdx.x & 31, ty = threadIdx.x >> 5;
    int pt = blockIdx.x, ct = blockIdx.y, b = blockIdx.z;
    const float* ip = in  + (size_t)b*NPB*64;
    float*       op = out + (size_t)b*64*NPB;
    #pragma unroll
    for(int r=0;r<4;r++){
        int p = pt*32 + ty + r*8;
        t[ty+r*8][tx] = ip[(size_t)p*64 + ct*32 + tx];
    }
    __syncthreads();
    #pragma unroll
    for(int r=0;r<4;r++){
        int c = ct*32 + ty + r*8;
        op[(size_t)c*NPB + (size_t)pt*32 + tx] = t[tx][ty+r*8];
    }
}

// ---------------- coalesced LayerNorm --------------------------------------
__global__ __launch_bounds__(256) void k_ln(const float* __restrict__ X,
        const float* __restrict__ g, const float* __restrict__ b,
        float* __restrict__ O){
    __shared__ float sx[128*66];
    __shared__ float smu2[128], srs[128];
    int t = threadIdx.x;
    size_t base = (size_t)blockIdx.x * 128;
    for(int s=t;s<4096;s+=256){
        int p = s >> 5, j2 = s & 31;
        float2 v = *(const float2*)(X + (base+p)*64 + j2*2);
        sx[p*66 + j2*2]   = v.x;
        sx[p*66 + j2*2+1] = v.y;
    }
    __syncthreads();
    if(t<128){
        float mu=0.f, m2=0.f;
        const float* r = sx + t*66;
        #pragma unroll 8
        for(int j=0;j<64;j++){ float v=r[j]; mu+=v; m2+=v*v; }
        mu *= (1.f/64.f);
        float var = fmaxf(m2*(1.f/64.f) - mu*mu, 0.f);
        smu2[t]=mu; srs[t]=rsqrtf(var+1e-5f);
    }
    __syncthreads();
    for(int s=t;s<4096;s+=256){
        int p = s >> 5, j2 = s & 31;
        float mu=smu2[p], rs=srs[p];
        int j = j2*2;
        float2 v;
        v.x = (sx[p*66+j]  -mu)*rs*g[j]  +b[j];
        v.y = (sx[p*66+j+1]-mu)*rs*g[j+1]+b[j+1];
        *(float2*)(O + (base+p)*64 + j) = v;
    }
}

// ---------------- gram partials --------------------------------------------
__global__ __launch_bounds__(256) void k_gram(const float* __restrict__ Q,
        const float* __restrict__ K, float* __restrict__ gpart){
    __shared__ float sq[4096], sk[4096];
    __shared__ float pS[1024];
    __shared__ float pn[128];
    int tid = threadIdx.x;
    int b = blockIdx.y;
    for(int i=tid;i<1024;i+=256) pS[i]=0.f;
    if(tid<128) pn[tid]=0.f;
    for(int t=0;t<8;t++){
        size_t base = ((size_t)b*NPB + (size_t)blockIdx.x*512 + t*64)*64;
        __syncthreads();
        for(int i=tid;i<4096;i+=256){ sq[i]=Q[base+i]; sk[i]=K[base+i]; }
        __syncthreads();
        #pragma unroll
        for(int jj=0;jj<4;jj++){
            int job = tid + jj*256;
            int h=job>>8, d=(job>>4)&15, e=job&15;
            int ck=h*16+d, cq=h*16+e;
            float acc=0.f;
            #pragma unroll 8
            for(int p=0;p<64;p++) acc += sk[p*64+ck]*sq[p*64+cq];
            pS[job]+=acc;
        }
        if(tid<128){
            int c=tid&63;
            const float* s = (tid<64)? sq : sk;
            float acc=0.f;
            #pragma unroll 8
            for(int p=0;p<64;p++){ float v=s[p*64+c]; acc+=v*v; }
            pn[tid]+=acc;
        }
    }
    __syncthreads();
    float* gp = gpart + ((size_t)b*128 + blockIdx.x)*1152;
    for(int i=tid;i<1024;i+=256) gp[i]=pS[i];
    if(tid<128) gp[1024+tid]=pn[tid];
}

// ---------------- attn softmax + fold into Mcomb ---------------------------
__global__ __launch_bounds__(256) void k_attn(const float* __restrict__ gpart,
        const float* __restrict__ Wp, const float* __restrict__ resc,
        float* __restrict__ Mcomb){
    __shared__ float sred[2304];
    __shared__ float sa[2048];
    int tid = threadIdx.x;
    for(int jj=tid;jj<2304;jj+=256){
        int b=jj/1152, j=jj-b*1152;
        float acc=0.f;
        for(int blk=0;blk<128;blk++) acc += gpart[((size_t)b*128+blk)*1152 + j];
        sred[jj]=acc;
    }
    __syncthreads();
    if(tid<128){
        int b=tid>>6, hd=tid&63, h=hd>>4, d=hd&15;
        float nk = fmaxf(sqrtf(sred[b*1152+1088+hd]),1e-6f);
        float r = resc[h];
        float row[16]; float mx=-1e30f;
        #pragma unroll
        for(int e=0;e<16;e++){
            float nq = fmaxf(sqrtf(sred[b*1152+1024+h*16+e]),1e-6f);
            float v = sred[b*1152 + h*256 + d*16 + e] / (nk*nq) * r;
            row[e]=v; mx=fmaxf(mx,v);
        }
        float s=0.f;
        #pragma unroll
        for(int e=0;e<16;e++){ row[e]=expf(row[e]-mx); s+=row[e]; }
        float inv=1.f/s;
        #pragma unroll
        for(int e=0;e<16;e++) sa[((b*4+h)*16+d)*16+e] = row[e]*inv;
    }
    __syncthreads();
    for(int job=tid;job<8192;job+=256){
        int b=job>>12, rem=job&4095, ci=rem>>6, co=rem&63;
        int h=ci>>4, e=ci&15;
        float acc=0.f;
        #pragma unroll
        for(int d=0;d<16;d++) acc += sa[((b*4+h)*16+d)*16+e] * Wp[(h*16+d)*64+co];
        Mcomb[job]=acc;
    }
}

// ---------------- mask gate (float4) ---------------------------------------
__global__ __launch_bounds__(256) void k_maskgate(const float* __restrict__ T,
        const float* __restrict__ M1, const float* __restrict__ V,
        const float* __restrict__ dw, const float* __restrict__ db,
        float* __restrict__ VG){
    __shared__ float4 sdw[400];
    __shared__ float4 sdb4[16];
    int tid=threadIdx.x;
    for(int i=tid;i<400;i+=256) sdw[i]=((const float4*)dw)[i];
    if(tid<16) sdb4[tid]=((const float4*)db)[tid];
    __syncthreads();
    size_t e=(size_t)blockIdx.x*256+tid;
    int c4=(int)(e&15);
    size_t p=e>>4;
    int b=(int)(p>>16);
    int pp=(int)(p&65535);
    int y=pp>>8, x=pp&255;
    float4 conv=make_float4(0,0,0,0);
    #pragma unroll
    for(int dy=0;dy<5;dy++){
        int yy=y+dy-2; if(yy<0||yy>255) continue;
        #pragma unroll
        for(int dx=0;dx<5;dx++){
            int xx=x+dx-2; if(xx<0||xx>255) continue;
            float4 tv = *(const float4*)(T + (((((size_t)b<<16)+(yy<<8)+xx)<<6)+c4*4));
            float4 wv = sdw[(dy*5+dx)*16+c4];
            conv.x+=tv.x*wv.x; conv.y+=tv.y*wv.y; conv.z+=tv.z*wv.z; conv.w+=tv.w*wv.w;
        }
    }
    float4 bb=sdb4[c4];
    float4 m1=((const float4*)M1)[e];
    float4 vv=((const float4*)V)[e];
    float4 r;
    r.x = vv.x*m1.x*(1.f+1.f/(1.f+expf(-(conv.x+bb.x))));
    r.y = vv.y*m1.y*(1.f+1.f/(1.f+expf(-(conv.y+bb.y))));
    r.z = vv.z*m1.z*(1.f+1.f/(1.f+expf(-(conv.z+bb.z))));
    r.w = vv.w*m1.w*(1.f+1.f/(1.f+expf(-(conv.w+bb.w))));
    ((float4*)VG)[e]=r;
}

// ---------------- depthwise 3x3 + GELU (float4) ----------------------------
__global__ __launch_bounds__(256) void k_dw3_gelu(const float* __restrict__ in,
        const float* __restrict__ dw, float* __restrict__ out, int cbits){
    __shared__ float4 sdw[576];
    int tid=threadIdx.x;
    int C4=1<<(cbits-2);
    for(int i=tid;i<9*C4;i+=256) sdw[i]=((const float4*)dw)[i];
    __syncthreads();
    size_t e=(size_t)blockIdx.x*256+tid;
    int c4=(int)(e&(C4-1));
    size_t p=e>>(cbits-2);
    int b=(int)(p>>16), pp=(int)(p&65535), y=pp>>8, x=pp&255;
    float4 conv=make_float4(0,0,0,0);
    #pragma unroll
    for(int dy=0;dy<3;dy++){
        int yy=y+dy-1; if(yy<0||yy>255) continue;
        #pragma unroll
        for(int dx=0;dx<3;dx++){
            int xx=x+dx-1; if(xx<0||xx>255) continue;
            float4 tv = *(const float4*)(in + ((((((size_t)b<<16)+(yy<<8)+xx))<<cbits)+c4*4));
            float4 wv = sdw[(dy*3+dx)*C4+c4];
            conv.x+=tv.x*wv.x; conv.y+=tv.y*wv.y; conv.z+=tv.z*wv.z; conv.w+=tv.w*wv.w;
        }
    }
    float4 r=make_float4(gelu_f(conv.x),gelu_f(conv.y),gelu_f(conv.z),gelu_f(conv.w));
    ((float4*)out)[e]=r;
}

// ---------------- msa epilogue: X += dw3(P, pe2) (float4) ------------------
__global__ __launch_bounds__(256) void k_msa_out(
        const float* __restrict__ P, const float* __restrict__ pe2,
        float* __restrict__ X){
    __shared__ float4 sdw[144];
    int tid=threadIdx.x;
    if(tid<144) sdw[tid]=((const float4*)pe2)[tid];
    __syncthreads();
    size_t e=(size_t)blockIdx.x*256+tid;
    int c4=(int)(e&15);
    size_t p=e>>4;
    int b=(int)(p>>16), pp=(int)(p&65535), y=pp>>8, x=pp&255;
    float4 conv=make_float4(0,0,0,0);
    #pragma unroll
    for(int dy=0;dy<3;dy++){
        int yy=y+dy-1; if(yy<0||yy>255) continue;
        #pragma unroll
        for(int dx=0;dx<3;dx++){
            int xx=x+dx-1; if(xx<0||xx>255) continue;
            float4 tv = *(const float4*)(P + (((((size_t)b<<16)+(yy<<8)+xx)<<6)+c4*4));
            float4 wv = sdw[(dy*3+dx)*16+c4];
            conv.x+=tv.x*wv.x; conv.y+=tv.y*wv.y; conv.z+=tv.z*wv.z; conv.w+=tv.w*wv.w;
        }
    }
    float4 xv=((float4*)X)[e];
    xv.x+=conv.x; xv.y+=conv.y; xv.z+=conv.z; xv.w+=conv.w;
    ((float4*)X)[e]=xv;
}

// ---------------- host -----------------------------------------------------
extern "C" void kernel_launch(void* const* d_in, const int* in_sizes, int n_in,
                              void* d_out, int out_size){
    const float* x    = (const float*)d_in[0];
    const float* mask = (const float*)d_in[1];
    const float* Wq   = (const float*)d_in[2];
    const float* Wk   = (const float*)d_in[3];
    const float* Wv   = (const float*)d_in[4];
    const float* resc = (const float*)d_in[5];
    const float* Wp   = (const float*)d_in[6];
    const float* bp   = (const float*)d_in[7];
    const float* pe1  = (const float*)d_in[8];
    const float* pe2  = (const float*)d_in[9];
    const float* mw1  = (const float*)d_in[10];
    const float* mb1  = (const float*)d_in[11];
    const float* mw2  = (const float*)d_in[12];
    const float* mb2  = (const float*)d_in[13];
    const float* mdw  = (const float*)d_in[14];
    const float* mdb  = (const float*)d_in[15];
    const float* lng  = (const float*)d_in[16];
    const float* lnb  = (const float*)d_in[17];
    const float* fw1  = (const float*)d_in[18];
    const float* fdw  = (const float*)d_in[19];
    const float* fw2  = (const float*)d_in[20];
    float* out = (float*)d_out;

    float *pX,*pM,*pQ,*pK,*pV,*pT1,*pH1,*pH2,*pGP,*pMC;
    cudaGetSymbolAddress((void**)&pX,  g_X);
    cudaGetSymbolAddress((void**)&pM,  g_Mk);
    cudaGetSymbolAddress((void**)&pQ,  g_Q);
    cudaGetSymbolAddress((void**)&pK,  g_K);
    cudaGetSymbolAddress((void**)&pV,  g_V);
    cudaGetSymbolAddress((void**)&pT1, g_T1);
    cudaGetSymbolAddress((void**)&pH1, g_H1);
    cudaGetSymbolAddress((void**)&pH2, g_H2);
    cudaGetSymbolAddress((void**)&pGP, g_GP);
    cudaGetSymbolAddress((void**)&pMC, g_MC);

    cudaFuncSetAttribute(k_tmma<1,1,0>, cudaFuncAttributeMaxDynamicSharedMemorySize, TM_SMEM);
    cudaFuncSetAttribute(k_tmma<1,1,2>, cudaFuncAttributeMaxDynamicSharedMemorySize, TM_SMEM);
    cudaFuncSetAttribute(k_tmma<1,4,1>, cudaFuncAttributeMaxDynamicSharedMemorySize, TM_SMEM);
    cudaFuncSetAttribute(k_tmma<4,1,2>, cudaFuncAttributeMaxDynamicSharedMemorySize, TM_SMEM);

    dim3 tg(2048,2,2);
    k_nchw2nhwc<<<tg,256>>>(x,    pX);
    k_nchw2nhwc<<<tg,256>>>(mask, pM);

    for(int i=0;i<3;i++){
        const float* Wq_i  = Wq  + i*4096;
        const float* Wk_i  = Wk  + i*4096;
        const float* Wv_i  = Wv  + i*4096;
        const float* Wp_i  = Wp  + i*4096;
        const float* mw1_i = mw1 + i*4096;
        const float* mw2_i = mw2 + i*4096;
        const float* bp_i  = bp  + i*64;
        const float* mb1_i = mb1 + i*64;
        const float* mb2_i = mb2 + i*64;
        const float* mdb_i = mdb + i*64;
        const float* lng_i = lng + i*64;
        const float* lnb_i = lnb + i*64;
        const float* pe1_i = pe1 + i*576;
        const float* pe2_i = pe2 + i*576;
        const float* mdw_i = mdw + i*1600;
        const float* rs_i  = resc+ i*4;
        const float* fw1_i = fw1 + i*64*256;
        const float* fdw_i = fdw + i*9*256;
        const float* fw2_i = fw2 + i*256*64;

        // attention stats path
        k_tmma<1,1,0><<<1024,128,TM_SMEM>>>(pX, 64, Wq_i, 64, 0, nullptr, pQ, 64);
        k_tmma<1,1,0><<<1024,128,TM_SMEM>>>(pX, 64, Wk_i, 64, 0, nullptr, pK, 64);
        k_gram<<<dim3(128,2),256>>>(pQ, pK, pGP);
        k_attn<<<1,256>>>(pGP, Wp_i, rs_i, pMC);
        // v + mask gate
        k_tmma<1,1,0><<<1024,128,TM_SMEM>>>(pX, 64, Wv_i, 64, 0, nullptr, pV, 64);
        k_tmma<1,1,0><<<1024,128,TM_SMEM>>>(pM, 64, mw1_i, 64, 0, mb1_i, pT1, 64);
        k_tmma<1,1,0><<<1024,128,TM_SMEM>>>(pT1, 64, mw2_i, 64, 0, mb2_i, pQ, 64);
        k_maskgate<<<8192,256>>>(pQ, pT1, pV, mdw_i, mdb_i, pT1);    // VG -> g_T1
        // positional path
        k_dw3_gelu<<<8192,256>>>(pV, pe1_i, pK, 6);                  // P -> g_K
        // folded attention apply + proj, added straight into X
        k_tmma<1,1,2><<<1024,128,TM_SMEM>>>(pT1, 64, pMC, 64, 4096, bp_i, pX, 64);
        k_msa_out<<<8192,256>>>(pK, pe2_i, pX);                      // X += dw3(P)
        // feed-forward
        k_ln<<<1024,256>>>(pX, lng_i, lnb_i, pT1);
        k_tmma<1,4,1><<<dim3(1024,1),128,TM_SMEM>>>(pT1, 64, fw1_i, 256, 0, nullptr, pH1, 256);
        k_dw3_gelu<<<32768,256>>>(pH1, fdw_i, pH2, 8);
        k_tmma<4,1,2><<<1024,128,TM_SMEM>>>(pH2, 256, fw2_i, 64, 0, nullptr, pX, 64);
    }

    k_nhwc2nchw<<<tg,256>>>(pX, out);
}